// round 2
// baseline (speedup 1.0000x reference)
#include <cuda_runtime.h>
#include <math.h>
#include <stdint.h>

// Problem constants
#define D      512
#define NNODES 20000
#define NEDGES 100000
#define EPRIME (NEDGES + NNODES)
#define H1v    8
#define C1v    64
#define H2v    4
#define C2v    128
#define CHUNK  256

// ---------------- scratch (device globals; no allocation allowed) -------------
__device__ float g_xp[(size_t)NNODES * D];      // xp1, then reused as xp2
__device__ float g_h[(size_t)NNODES * D];       // hidden after layer 1
__device__ float g_asrc[(size_t)NNODES * H1v];
__device__ float g_adst[(size_t)NNODES * H1v];
__device__ float g_e[(size_t)EPRIME * H1v];     // edge scores (reused layer 2)
__device__ float g_logits[(size_t)NNODES * C2v];
__device__ int   g_deg[NNODES];
__device__ int   g_rowoff[NNODES + 1];
__device__ int   g_cursor[NNODES];
__device__ int   g_csr[EPRIME];
__device__ float g_accum[2];
__device__ int   g_mask_byte;

// ---------------- helpers ----------------------------------------------------
__device__ __forceinline__ float warp_max(float v) {
    #pragma unroll
    for (int o = 16; o; o >>= 1) v = fmaxf(v, __shfl_xor_sync(0xffffffffu, v, o));
    return v;
}
__device__ __forceinline__ float warp_sum(float v) {
    #pragma unroll
    for (int o = 16; o; o >>= 1) v += __shfl_xor_sync(0xffffffffu, v, o);
    return v;
}

// ---------------- init / CSR build -------------------------------------------
__global__ void init_kernel(int N) {
    int i = blockIdx.x * blockDim.x + threadIdx.x;
    if (i < N) g_deg[i] = 0;
    if (i == 0) { g_accum[0] = 0.f; g_accum[1] = 0.f; g_mask_byte = 0; }
}

__global__ void detect_mask_kernel(const unsigned int* __restrict__ m, int nwords) {
    int i = blockIdx.x * blockDim.x + threadIdx.x;
    if (i < nwords) {
        unsigned v = m[i];
        if (v != 0u && v != 1u && v != 0x3F800000u) atomicOr(&g_mask_byte, 1);
    }
}

__global__ void hist_kernel(const int* __restrict__ ei, int E, int N) {
    int i = blockIdx.x * blockDim.x + threadIdx.x;
    if (i >= E + N) return;
    int d = (i < E) ? ei[E + i] : (i - E);
    atomicAdd(&g_deg[d], 1);
}

__global__ void scan_kernel(int N) {
    __shared__ int sh[1024];
    __shared__ int carry;
    int tid = threadIdx.x;
    if (tid == 0) carry = 0;
    __syncthreads();
    for (int base = 0; base < N; base += 1024) {
        int i = base + tid;
        int v = (i < N) ? g_deg[i] : 0;
        sh[tid] = v;
        __syncthreads();
        for (int off = 1; off < 1024; off <<= 1) {
            int t = (tid >= off) ? sh[tid - off] : 0;
            __syncthreads();
            sh[tid] += t;
            __syncthreads();
        }
        int incl = sh[tid] + carry;
        if (i < N) g_rowoff[i + 1] = incl;
        __syncthreads();
        if (tid == 1023) carry = incl;
        __syncthreads();
    }
    if (tid == 0) g_rowoff[0] = 0;
}

__global__ void cursor_kernel(int N) {
    int i = blockIdx.x * blockDim.x + threadIdx.x;
    if (i < N) g_cursor[i] = g_rowoff[i];
}

__global__ void scatter_kernel(const int* __restrict__ ei, int E, int N) {
    int i = blockIdx.x * blockDim.x + threadIdx.x;
    if (i >= E + N) return;
    int d = (i < E) ? ei[E + i] : (i - E);
    int pos = atomicAdd(&g_cursor[d], 1);
    g_csr[pos] = i;
}

// ---------------- fp32 tiled GEMM: C[M,512] = A[M,512] @ B[512,512] ----------
__global__ __launch_bounds__(256, 2)
void gemm_kernel(const float* __restrict__ A, const float* __restrict__ B,
                 float* __restrict__ C, int M) {
    const int K = D, Nc = D;
    __shared__ float As[16][132];
    __shared__ float Bs[16][128];
    int t  = threadIdx.x;
    int m0 = blockIdx.y * 128, n0 = blockIdx.x * 128;
    int ty = t >> 4, tx = t & 15;
    int ar = t >> 2, akv = t & 3;
    int bk = t >> 5, bnv = t & 31;

    float acc[8][8];
    #pragma unroll
    for (int i = 0; i < 8; i++)
        #pragma unroll
        for (int j = 0; j < 8; j++) acc[i][j] = 0.f;

    for (int k0 = 0; k0 < K; k0 += 16) {
        #pragma unroll
        for (int i = 0; i < 2; i++) {
            int m = ar + 64 * i;
            float4 v = make_float4(0.f, 0.f, 0.f, 0.f);
            if (m0 + m < M)
                v = *(const float4*)(A + (size_t)(m0 + m) * K + k0 + akv * 4);
            As[akv * 4 + 0][m] = v.x;
            As[akv * 4 + 1][m] = v.y;
            As[akv * 4 + 2][m] = v.z;
            As[akv * 4 + 3][m] = v.w;
        }
        #pragma unroll
        for (int i = 0; i < 2; i++) {
            float4 v = *(const float4*)(B + (size_t)(k0 + bk + 8 * i) * Nc + n0 + bnv * 4);
            *(float4*)&Bs[bk + 8 * i][bnv * 4] = v;
        }
        __syncthreads();
        #pragma unroll
        for (int k = 0; k < 16; k++) {
            float a[8], b[8];
            *(float4*)&a[0] = *(const float4*)&As[k][ty * 8];
            *(float4*)&a[4] = *(const float4*)&As[k][ty * 8 + 4];
            *(float4*)&b[0] = *(const float4*)&Bs[k][tx * 8];
            *(float4*)&b[4] = *(const float4*)&Bs[k][tx * 8 + 4];
            #pragma unroll
            for (int i = 0; i < 8; i++)
                #pragma unroll
                for (int j = 0; j < 8; j++)
                    acc[i][j] += a[i] * b[j];
        }
        __syncthreads();
    }
    #pragma unroll
    for (int i = 0; i < 8; i++) {
        int m = m0 + ty * 8 + i;
        if (m < M) {
            float* cp = C + (size_t)m * Nc + n0 + tx * 8;
            *(float4*)cp       = make_float4(acc[i][0], acc[i][1], acc[i][2], acc[i][3]);
            *(float4*)(cp + 4) = make_float4(acc[i][4], acc[i][5], acc[i][6], acc[i][7]);
        }
    }
}

// ---------------- per-node attention dot products ----------------------------
__global__ void att_kernel(const float* __restrict__ xp,
                           const float* __restrict__ a_src, const float* __restrict__ a_dst,
                           float* __restrict__ asrc, float* __restrict__ adst,
                           int N, int H, int C) {
    int warp = (blockIdx.x * blockDim.x + threadIdx.x) >> 5;
    int lane = threadIdx.x & 31;
    if (warp >= N) return;
    const float* row = xp + (size_t)warp * D;
    for (int h = 0; h < H; h++) {
        float ss = 0.f, sd = 0.f;
        for (int j = lane; j < C; j += 32) {
            float xv = row[h * C + j];
            ss += xv * a_src[h * C + j];
            sd += xv * a_dst[h * C + j];
        }
        ss = warp_sum(ss);
        sd = warp_sum(sd);
        if (lane == 0) { asrc[warp * H + h] = ss; adst[warp * H + h] = sd; }
    }
}

// ---------------- per-edge leaky-relu scores ---------------------------------
__global__ void score_kernel(const float* __restrict__ asrc, const float* __restrict__ adst,
                             const int* __restrict__ ei, int E, int N, int H) {
    int i = blockIdx.x * blockDim.x + threadIdx.x;
    if (i >= E + N) return;
    int s, d;
    if (i < E) { s = ei[i]; d = ei[E + i]; } else { s = d = i - E; }
    for (int h = 0; h < H; h++) {
        float v = asrc[s * H + h] + adst[d * H + h];
        g_e[(size_t)i * H + h] = v > 0.f ? v : 0.2f * v;
    }
}

// ---------------- per-dst softmax + aggregate (block per node) ---------------
// mode 0: out[n, H*C] = elu(agg + bias)         (layer 1, concat)
// mode 1: out[n, C]   = mean_h(agg) + bias      (layer 2)
__global__ __launch_bounds__(256)
void agg_kernel(const float* __restrict__ xp, const float* __restrict__ e,
                const float* __restrict__ bias, float* __restrict__ out,
                const int* __restrict__ ei, int E, int H, int C, int mode) {
    __shared__ float sh_alpha[CHUNK * H1v];
    __shared__ int   sh_src[CHUNK];
    __shared__ float sh_m[H1v], sh_s[H1v];
    __shared__ float sh_red[512];
    int n = blockIdx.x;
    int tid = threadIdx.x;
    int w = tid >> 5, lane = tid & 31;
    int beg = g_rowoff[n], end = g_rowoff[n + 1];

    if (w < H) {
        float m = -1e30f;
        for (int i = beg + lane; i < end; i += 32)
            m = fmaxf(m, e[(size_t)g_csr[i] * H + w]);
        m = warp_max(m);
        float s = 0.f;
        for (int i = beg + lane; i < end; i += 32)
            s += expf(e[(size_t)g_csr[i] * H + w] - m);
        s = warp_sum(s);
        if (lane == 0) { sh_m[w] = m; sh_s[w] = s + 1e-16f; }
    }
    __syncthreads();

    int h0 = tid / C, h1 = (tid + 256) / C;
    float acc0 = 0.f, acc1 = 0.f;
    for (int cs = beg; cs < end; cs += CHUNK) {
        int cn = min(CHUNK, end - cs);
        for (int idx = tid; idx < cn; idx += 256) {
            int eid = g_csr[cs + idx];
            sh_src[idx] = (eid < E) ? ei[eid] : (eid - E);
        }
        for (int idx = tid; idx < cn * H; idx += 256) {
            int i = idx / H, h = idx - i * H;
            int eid = g_csr[cs + i];
            sh_alpha[i * H + h] = expf(e[(size_t)eid * H + h] - sh_m[h]) / sh_s[h];
        }
        __syncthreads();
        for (int i = 0; i < cn; i++) {
            const float* row = xp + (size_t)sh_src[i] * D;
            acc0 += sh_alpha[i * H + h0] * row[tid];
            acc1 += sh_alpha[i * H + h1] * row[tid + 256];
        }
        __syncthreads();
    }

    if (mode == 0) {
        float v0 = acc0 + bias[tid];
        float v1 = acc1 + bias[tid + 256];
        out[(size_t)n * D + tid]       = v0 > 0.f ? v0 : expm1f(v0);
        out[(size_t)n * D + tid + 256] = v1 > 0.f ? v1 : expm1f(v1);
    } else {
        sh_red[tid] = acc0;
        sh_red[tid + 256] = acc1;
        __syncthreads();
        if (tid < C) {
            float s = 0.f;
            for (int h = 0; h < H; h++) s += sh_red[h * C + tid];
            out[(size_t)n * C + tid] = s / (float)H + bias[tid];
        }
    }
}

// ---------------- loss --------------------------------------------------------
__global__ void copy_out_kernel(float* __restrict__ dst, int count) {
    int i = blockIdx.x * blockDim.x + threadIdx.x;
    if (i < count) dst[i] = g_logits[i];
}

__global__ __launch_bounds__(128)
void loss_kernel(const int* __restrict__ y, const int* __restrict__ mask, int N) {
    __shared__ float red[128];
    int tid = threadIdx.x;
    float lce = 0.f, lw = 0.f;
    int byte_mode = g_mask_byte;
    for (int n = blockIdx.x; n < N; n += gridDim.x) {
        float v = g_logits[(size_t)n * C2v + tid];
        red[tid] = v;
        __syncthreads();
        #pragma unroll
        for (int o = 64; o; o >>= 1) {
            if (tid < o) red[tid] = fmaxf(red[tid], red[tid + o]);
            __syncthreads();
        }
        float m = red[0];
        __syncthreads();
        red[tid] = expf(v - m);
        __syncthreads();
        #pragma unroll
        for (int o = 64; o; o >>= 1) {
            if (tid < o) red[tid] += red[tid + o];
            __syncthreads();
        }
        if (tid == 0) {
            bool mv = byte_mode ? (((const unsigned char*)mask)[n] != 0) : (mask[n] != 0);
            if (mv) {
                float lse = m + logf(red[0]);
                lce += lse - g_logits[(size_t)n * C2v + y[n]];
                lw += 1.f;
            }
        }
        __syncthreads();
    }
    if (tid == 0) {
        atomicAdd(&g_accum[0], lce);
        atomicAdd(&g_accum[1], lw);
    }
}

__global__ void finalize_kernel(float* d_out, int write_loss) {
    if (write_loss) d_out[0] = g_accum[0] / g_accum[1];
}

// ---------------- launch ------------------------------------------------------
extern "C" void kernel_launch(void* const* d_in, const int* in_sizes, int n_in,
                              void* d_out, int out_size) {
    const float* x       = (const float*)d_in[0];
    const int*   ei      = (const int*)d_in[1];
    const int*   y       = (const int*)d_in[2];
    const int*   mask    = (const int*)d_in[3];
    const float* W1      = (const float*)d_in[4];
    const float* att_s1  = (const float*)d_in[5];
    const float* att_d1  = (const float*)d_in[6];
    const float* b1      = (const float*)d_in[7];
    const float* W2      = (const float*)d_in[8];
    const float* att_s2  = (const float*)d_in[9];
    const float* att_d2  = (const float*)d_in[10];
    const float* b2      = (const float*)d_in[11];
    float* out_f = (float*)d_out;

    int N = in_sizes[0] / D;        // 20000
    int E = in_sizes[1] / 2;        // 100000
    int EP = E + N;

    float *p_xp, *p_h, *p_asrc, *p_adst, *p_e, *p_logits;
    cudaGetSymbolAddress((void**)&p_xp, g_xp);
    cudaGetSymbolAddress((void**)&p_h, g_h);
    cudaGetSymbolAddress((void**)&p_asrc, g_asrc);
    cudaGetSymbolAddress((void**)&p_adst, g_adst);
    cudaGetSymbolAddress((void**)&p_e, g_e);
    cudaGetSymbolAddress((void**)&p_logits, g_logits);

    int has_loss = (out_size == N * C2v + 1) ? 1 : 0;
    int out_count = out_size - has_loss;
    if (out_count > N * C2v) out_count = N * C2v;

    // --- CSR build (shared by both layers) ---
    init_kernel<<<(N + 255) / 256, 256>>>(N);
    detect_mask_kernel<<<(N / 4 + 255) / 256, 256>>>((const unsigned int*)mask, N / 4);
    hist_kernel<<<(EP + 255) / 256, 256>>>(ei, E, N);
    scan_kernel<<<1, 1024>>>(N);
    cursor_kernel<<<(N + 255) / 256, 256>>>(N);
    scatter_kernel<<<(EP + 255) / 256, 256>>>(ei, E, N);

    dim3 ggrid(D / 128, (N + 127) / 128);

    // --- layer 1 ---
    gemm_kernel<<<ggrid, 256>>>(x, W1, p_xp, N);
    att_kernel<<<(N + 7) / 8, 256>>>(p_xp, att_s1, att_d1, p_asrc, p_adst, N, H1v, C1v);
    score_kernel<<<(EP + 255) / 256, 256>>>(p_asrc, p_adst, ei, E, N, H1v);
    agg_kernel<<<N, 256>>>(p_xp, p_e, b1, p_h, ei, E, H1v, C1v, 0);

    // --- layer 2 ---
    gemm_kernel<<<ggrid, 256>>>(p_h, W2, p_xp, N);
    att_kernel<<<(N + 7) / 8, 256>>>(p_xp, att_s2, att_d2, p_asrc, p_adst, N, H2v, C2v);
    score_kernel<<<(EP + 255) / 256, 256>>>(p_asrc, p_adst, ei, E, N, H2v);
    agg_kernel<<<N, 256>>>(p_xp, p_e, b2, p_logits, ei, E, H2v, C2v, 1);

    // --- output + loss ---
    copy_out_kernel<<<(out_count + 255) / 256, 256>>>(out_f + has_loss, out_count);
    loss_kernel<<<1024, 128>>>(y, mask, N);
    finalize_kernel<<<1, 1>>>(out_f, has_loss);
}

// round 3
// speedup vs baseline: 1.4571x; 1.4571x over previous
#include <cuda_runtime.h>
#include <cuda_bf16.h>
#include <math.h>
#include <stdint.h>

// Problem constants
#define D      512
#define NNODES 20000
#define NEDGES 100000
#define EPRIME (NEDGES + NNODES)
#define H1v    8
#define C1v    64
#define H2v    4
#define C2v    128
#define CHUNK  256

// ---------------- scratch (device globals; no allocation allowed) -------------
__device__ float g_xp[(size_t)NNODES * D];      // xp1, then reused as xp2
__device__ float g_h[(size_t)NNODES * D];       // hidden after layer 1
__device__ float g_asrc[(size_t)NNODES * H1v];
__device__ float g_adst[(size_t)NNODES * H1v];
__device__ float g_e[(size_t)EPRIME * H1v];     // edge scores (reused layer 2)
__device__ float g_logits[(size_t)NNODES * C2v];
__device__ int   g_deg[NNODES];
__device__ int   g_rowstart[NNODES];
__device__ int   g_cursor[NNODES];
__device__ int   g_csr[EPRIME];
__device__ float g_accum[2];
__device__ int   g_mask_byte;
__device__ int   g_total;
// bf16 hi/lo split buffers for tensor-core GEMM
__device__ __nv_bfloat16 g_Ahi[(size_t)NNODES * D];
__device__ __nv_bfloat16 g_Alo[(size_t)NNODES * D];
__device__ __nv_bfloat16 g_Bhi[(size_t)D * D];
__device__ __nv_bfloat16 g_Blo[(size_t)D * D];

// ---------------- helpers ----------------------------------------------------
__device__ __forceinline__ float warp_max(float v) {
    #pragma unroll
    for (int o = 16; o; o >>= 1) v = fmaxf(v, __shfl_xor_sync(0xffffffffu, v, o));
    return v;
}
__device__ __forceinline__ float warp_sum(float v) {
    #pragma unroll
    for (int o = 16; o; o >>= 1) v += __shfl_xor_sync(0xffffffffu, v, o);
    return v;
}

__device__ __forceinline__ void mma16816(float* c, const uint32_t* a, const uint32_t* b) {
    asm volatile(
        "mma.sync.aligned.m16n8k16.row.col.f32.bf16.bf16.f32 "
        "{%0,%1,%2,%3}, {%4,%5,%6,%7}, {%8,%9}, {%0,%1,%2,%3};\n"
        : "+f"(c[0]), "+f"(c[1]), "+f"(c[2]), "+f"(c[3])
        : "r"(a[0]), "r"(a[1]), "r"(a[2]), "r"(a[3]), "r"(b[0]), "r"(b[1]));
}
__device__ __forceinline__ void ldsm4(uint32_t* r, uint32_t addr) {
    asm volatile("ldmatrix.sync.aligned.m8n8.x4.shared.b16 {%0,%1,%2,%3}, [%4];\n"
        : "=r"(r[0]), "=r"(r[1]), "=r"(r[2]), "=r"(r[3]) : "r"(addr));
}
__device__ __forceinline__ void ldsm4t(uint32_t* r, uint32_t addr) {
    asm volatile("ldmatrix.sync.aligned.m8n8.x4.trans.shared.b16 {%0,%1,%2,%3}, [%4];\n"
        : "=r"(r[0]), "=r"(r[1]), "=r"(r[2]), "=r"(r[3]) : "r"(addr));
}
__device__ __forceinline__ void cpasync16(uint32_t dst, const void* src, int srcsize) {
    asm volatile("cp.async.cg.shared.global [%0], [%1], 16, %2;\n"
        :: "r"(dst), "l"(src), "r"(srcsize));
}
__device__ __forceinline__ void cp_commit() {
    asm volatile("cp.async.commit_group;\n");
}
template<int NW> __device__ __forceinline__ void cp_wait() {
    asm volatile("cp.async.wait_group %0;\n" :: "n"(NW));
}

// ---------------- init / CSR build -------------------------------------------
__global__ void init_kernel(int N) {
    int i = blockIdx.x * blockDim.x + threadIdx.x;
    if (i < N) g_deg[i] = 0;
    if (i == 0) { g_accum[0] = 0.f; g_accum[1] = 0.f; g_mask_byte = 0; g_total = 0; }
}

__global__ void detect_mask_kernel(const unsigned int* __restrict__ m, int nwords) {
    int i = blockIdx.x * blockDim.x + threadIdx.x;
    if (i < nwords) {
        unsigned v = m[i];
        if (v != 0u && v != 1u && v != 0x3F800000u) atomicOr(&g_mask_byte, 1);
    }
}

__global__ void hist_kernel(const int* __restrict__ ei, int E, int N) {
    int i = blockIdx.x * blockDim.x + threadIdx.x;
    if (i >= E + N) return;
    int d = (i < E) ? ei[E + i] : (i - E);
    atomicAdd(&g_deg[d], 1);
}

// Assign each node a contiguous segment (placement order is immaterial)
__global__ void offsets_kernel(int N) {
    int i = blockIdx.x * blockDim.x + threadIdx.x;
    if (i < N) {
        int base = atomicAdd(&g_total, g_deg[i]);
        g_rowstart[i] = base;
        g_cursor[i] = base;
    }
}

__global__ void scatter_kernel(const int* __restrict__ ei, int E, int N) {
    int i = blockIdx.x * blockDim.x + threadIdx.x;
    if (i >= E + N) return;
    int d = (i < E) ? ei[E + i] : (i - E);
    int pos = atomicAdd(&g_cursor[d], 1);
    g_csr[pos] = i;
}

// ---------------- bf16 hi/lo split --------------------------------------------
__global__ void split_kernel(const float* __restrict__ x,
                             __nv_bfloat16* __restrict__ hi,
                             __nv_bfloat16* __restrict__ lo, int n) {
    for (int i = blockIdx.x * blockDim.x + threadIdx.x; i < n; i += gridDim.x * blockDim.x) {
        float v = x[i];
        __nv_bfloat16 h = __float2bfloat16(v);
        hi[i] = h;
        lo[i] = __float2bfloat16(v - __bfloat162float(h));
    }
}

// ---------------- tensor-core GEMM: C[M,512] = A[M,512] @ B[512,512] -----------
// bf16 hi/lo split, 3 products into fp32 accumulators via mma.m16n8k16
#define LDA_S 40     // 32 + 8 pad (elems)
#define LDB_S 136    // 128 + 8 pad (elems)
#define A_HI_OFF 0
#define A_LO_OFF (128 * LDA_S * 2)                    // 10240
#define B_HI_OFF (A_LO_OFF * 2)                       // 20480
#define B_LO_OFF (B_HI_OFF + 32 * LDB_S * 2)          // 29184
#define STAGE_BYTES (B_LO_OFF + 32 * LDB_S * 2)       // 37888
#define GEMM_SMEM (2 * STAGE_BYTES)                   // 75776

extern __shared__ char smem_raw[];

__global__ __launch_bounds__(256, 1)
void gemm_mma_kernel(const __nv_bfloat16* __restrict__ Ahi,
                     const __nv_bfloat16* __restrict__ Alo,
                     const __nv_bfloat16* __restrict__ Bhi,
                     const __nv_bfloat16* __restrict__ Blo,
                     float* __restrict__ C, int M) {
    const int tid = threadIdx.x;
    const int lane = tid & 31;
    const int wid = tid >> 5;
    const int m0 = blockIdx.y * 128;
    const int n0 = blockIdx.x * 128;
    const int warp_m = wid >> 2;          // 0..1 -> 64 rows
    const int warp_n = wid & 3;           // 0..3 -> 32 cols
    const int m_base = warp_m * 64;
    const int n_base = warp_n * 32;

    uint32_t smem_u32 = (uint32_t)__cvta_generic_to_shared(smem_raw);

    // per-thread load slots
    const int arow0 = tid >> 2, acol0 = (tid & 3) * 8;         // + row 64 for second chunk
    const int brow0 = tid >> 4, bcol0 = (tid & 15) * 8;        // + row 16 for second chunk

    float acc[4][4][4];
    #pragma unroll
    for (int i = 0; i < 4; i++)
        #pragma unroll
        for (int j = 0; j < 4; j++)
            #pragma unroll
            for (int k = 0; k < 4; k++) acc[i][j][k] = 0.f;

    const int NIT = D / 32;   // 16

    auto load_stage = [&](int it, int s) {
        int k0 = it * 32;
        uint32_t base = smem_u32 + s * STAGE_BYTES;
        #pragma unroll
        for (int c = 0; c < 2; c++) {
            int row = arow0 + c * 64;
            int gr = m0 + row;
            int ok = (gr < M) ? 16 : 0;
            size_t goff = (size_t)gr * D + k0 + acol0;
            uint32_t soff = (uint32_t)(row * LDA_S + acol0) * 2;
            cpasync16(base + A_HI_OFF + soff, Ahi + goff, ok);
            cpasync16(base + A_LO_OFF + soff, Alo + goff, ok);
        }
        #pragma unroll
        for (int c = 0; c < 2; c++) {
            int row = brow0 + c * 16;
            size_t goff = (size_t)(k0 + row) * D + n0 + bcol0;
            uint32_t soff = (uint32_t)(row * LDB_S + bcol0) * 2;
            cpasync16(base + B_HI_OFF + soff, Bhi + goff, 16);
            cpasync16(base + B_LO_OFF + soff, Blo + goff, 16);
        }
    };

    load_stage(0, 0);
    cp_commit();

    for (int it = 0; it < NIT; it++) {
        if (it + 1 < NIT) {
            load_stage(it + 1, (it + 1) & 1);
            cp_commit();
            cp_wait<1>();
        } else {
            cp_wait<0>();
        }
        __syncthreads();

        uint32_t stg = smem_u32 + (it & 1) * STAGE_BYTES;
        #pragma unroll
        for (int kk = 0; kk < 2; kk++) {
            int kof = kk * 16;
            uint32_t ahi[4][4], alo[4][4];
            #pragma unroll
            for (int mt = 0; mt < 4; mt++) {
                uint32_t off = (uint32_t)((m_base + mt * 16 + (lane & 15)) * LDA_S
                                          + kof + 8 * (lane >> 4)) * 2;
                ldsm4(ahi[mt], stg + A_HI_OFF + off);
                ldsm4(alo[mt], stg + A_LO_OFF + off);
            }
            uint32_t bhi[4][2], blo[4][2];
            #pragma unroll
            for (int p = 0; p < 2; p++) {
                uint32_t off = (uint32_t)((kof + (lane & 7) + 8 * ((lane >> 3) & 1)) * LDB_S
                                          + n_base + p * 16 + 8 * (lane >> 4)) * 2;
                uint32_t r[4];
                ldsm4t(r, stg + B_HI_OFF + off);
                bhi[p * 2][0] = r[0]; bhi[p * 2][1] = r[1];
                bhi[p * 2 + 1][0] = r[2]; bhi[p * 2 + 1][1] = r[3];
                ldsm4t(r, stg + B_LO_OFF + off);
                blo[p * 2][0] = r[0]; blo[p * 2][1] = r[1];
                blo[p * 2 + 1][0] = r[2]; blo[p * 2 + 1][1] = r[3];
            }
            #pragma unroll
            for (int mt = 0; mt < 4; mt++)
                #pragma unroll
                for (int nt = 0; nt < 4; nt++) {
                    mma16816(acc[mt][nt], ahi[mt], bhi[nt]);
                    mma16816(acc[mt][nt], ahi[mt], blo[nt]);
                    mma16816(acc[mt][nt], alo[mt], bhi[nt]);
                }
        }
        __syncthreads();
    }

    // epilogue
    const int gid = lane >> 2, t4 = lane & 3;
    #pragma unroll
    for (int mt = 0; mt < 4; mt++) {
        int r0 = m0 + m_base + mt * 16 + gid;
        int r1 = r0 + 8;
        #pragma unroll
        for (int nt = 0; nt < 4; nt++) {
            int col = n0 + n_base + nt * 8 + t4 * 2;
            if (r0 < M) *(float2*)&C[(size_t)r0 * D + col] = make_float2(acc[mt][nt][0], acc[mt][nt][1]);
            if (r1 < M) *(float2*)&C[(size_t)r1 * D + col] = make_float2(acc[mt][nt][2], acc[mt][nt][3]);
        }
    }
}

// ---------------- per-node attention dot products ----------------------------
__global__ void att_kernel(const float* __restrict__ xp,
                           const float* __restrict__ a_src, const float* __restrict__ a_dst,
                           float* __restrict__ asrc, float* __restrict__ adst,
                           int N, int H, int C) {
    int warp = (blockIdx.x * blockDim.x + threadIdx.x) >> 5;
    int lane = threadIdx.x & 31;
    if (warp >= N) return;
    const float* row = xp + (size_t)warp * D;
    for (int h = 0; h < H; h++) {
        float ss = 0.f, sd = 0.f;
        for (int j = lane; j < C; j += 32) {
            float xv = row[h * C + j];
            ss += xv * a_src[h * C + j];
            sd += xv * a_dst[h * C + j];
        }
        ss = warp_sum(ss);
        sd = warp_sum(sd);
        if (lane == 0) { asrc[warp * H + h] = ss; adst[warp * H + h] = sd; }
    }
}

// ---------------- per-edge leaky-relu scores ---------------------------------
__global__ void score_kernel(const float* __restrict__ asrc, const float* __restrict__ adst,
                             const int* __restrict__ ei, int E, int N, int H) {
    int i = blockIdx.x * blockDim.x + threadIdx.x;
    if (i >= E + N) return;
    int s, d;
    if (i < E) { s = ei[i]; d = ei[E + i]; } else { s = d = i - E; }
    for (int h = 0; h < H; h++) {
        float v = asrc[s * H + h] + adst[d * H + h];
        g_e[(size_t)i * H + h] = v > 0.f ? v : 0.2f * v;
    }
}

// ---------------- per-dst softmax + aggregate (block per node) ---------------
__global__ __launch_bounds__(256)
void agg_kernel(const float* __restrict__ xp, const float* __restrict__ e,
                const float* __restrict__ bias, float* __restrict__ out,
                const int* __restrict__ ei, int E, int H, int C, int mode) {
    __shared__ float sh_alpha[CHUNK * H1v];
    __shared__ int   sh_src[CHUNK];
    __shared__ float sh_m[H1v], sh_s[H1v];
    __shared__ float sh_red[512];
    int n = blockIdx.x;
    int tid = threadIdx.x;
    int w = tid >> 5, lane = tid & 31;
    int beg = g_rowstart[n], end = beg + g_deg[n];

    if (w < H) {
        float m = -1e30f;
        for (int i = beg + lane; i < end; i += 32)
            m = fmaxf(m, e[(size_t)g_csr[i] * H + w]);
        m = warp_max(m);
        float s = 0.f;
        for (int i = beg + lane; i < end; i += 32)
            s += expf(e[(size_t)g_csr[i] * H + w] - m);
        s = warp_sum(s);
        if (lane == 0) { sh_m[w] = m; sh_s[w] = s + 1e-16f; }
    }
    __syncthreads();

    int h0 = tid / C, h1 = (tid + 256) / C;
    float acc0 = 0.f, acc1 = 0.f;
    for (int cs = beg; cs < end; cs += CHUNK) {
        int cn = min(CHUNK, end - cs);
        for (int idx = tid; idx < cn; idx += 256) {
            int eid = g_csr[cs + idx];
            sh_src[idx] = (eid < E) ? ei[eid] : (eid - E);
        }
        for (int idx = tid; idx < cn * H; idx += 256) {
            int i = idx / H, h = idx - i * H;
            int eid = g_csr[cs + i];
            sh_alpha[i * H + h] = expf(e[(size_t)eid * H + h] - sh_m[h]) / sh_s[h];
        }
        __syncthreads();
        for (int i = 0; i < cn; i++) {
            const float* row = xp + (size_t)sh_src[i] * D;
            acc0 += sh_alpha[i * H + h0] * row[tid];
            acc1 += sh_alpha[i * H + h1] * row[tid + 256];
        }
        __syncthreads();
    }

    if (mode == 0) {
        float v0 = acc0 + bias[tid];
        float v1 = acc1 + bias[tid + 256];
        out[(size_t)n * D + tid]       = v0 > 0.f ? v0 : expm1f(v0);
        out[(size_t)n * D + tid + 256] = v1 > 0.f ? v1 : expm1f(v1);
    } else {
        sh_red[tid] = acc0;
        sh_red[tid + 256] = acc1;
        __syncthreads();
        if (tid < C) {
            float s = 0.f;
            for (int h = 0; h < H; h++) s += sh_red[h * C + tid];
            out[(size_t)n * C + tid] = s / (float)H + bias[tid];
        }
    }
}

// ---------------- loss --------------------------------------------------------
__global__ void copy_out_kernel(float* __restrict__ dst, int count) {
    int i = blockIdx.x * blockDim.x + threadIdx.x;
    if (i < count) dst[i] = g_logits[i];
}

__global__ __launch_bounds__(128)
void loss_kernel(const int* __restrict__ y, const int* __restrict__ mask, int N) {
    __shared__ float red[128];
    int tid = threadIdx.x;
    float lce = 0.f, lw = 0.f;
    int byte_mode = g_mask_byte;
    for (int n = blockIdx.x; n < N; n += gridDim.x) {
        float v = g_logits[(size_t)n * C2v + tid];
        red[tid] = v;
        __syncthreads();
        #pragma unroll
        for (int o = 64; o; o >>= 1) {
            if (tid < o) red[tid] = fmaxf(red[tid], red[tid + o]);
            __syncthreads();
        }
        float m = red[0];
        __syncthreads();
        red[tid] = expf(v - m);
        __syncthreads();
        #pragma unroll
        for (int o = 64; o; o >>= 1) {
            if (tid < o) red[tid] += red[tid + o];
            __syncthreads();
        }
        if (tid == 0) {
            bool mv = byte_mode ? (((const unsigned char*)mask)[n] != 0) : (mask[n] != 0);
            if (mv) {
                float lse = m + logf(red[0]);
                lce += lse - g_logits[(size_t)n * C2v + y[n]];
                lw += 1.f;
            }
        }
        __syncthreads();
    }
    if (tid == 0) {
        atomicAdd(&g_accum[0], lce);
        atomicAdd(&g_accum[1], lw);
    }
}

__global__ void finalize_kernel(float* d_out, int write_loss) {
    if (write_loss) d_out[0] = g_accum[0] / g_accum[1];
}

// ---------------- launch ------------------------------------------------------
extern "C" void kernel_launch(void* const* d_in, const int* in_sizes, int n_in,
                              void* d_out, int out_size) {
    const float* x       = (const float*)d_in[0];
    const int*   ei      = (const int*)d_in[1];
    const int*   y       = (const int*)d_in[2];
    const int*   mask    = (const int*)d_in[3];
    const float* W1      = (const float*)d_in[4];
    const float* att_s1  = (const float*)d_in[5];
    const float* att_d1  = (const float*)d_in[6];
    const float* b1      = (const float*)d_in[7];
    const float* W2      = (const float*)d_in[8];
    const float* att_s2  = (const float*)d_in[9];
    const float* att_d2  = (const float*)d_in[10];
    const float* b2      = (const float*)d_in[11];
    float* out_f = (float*)d_out;

    int N = in_sizes[0] / D;        // 20000
    int E = in_sizes[1] / 2;        // 100000
    int EP = E + N;

    float *p_xp, *p_h, *p_asrc, *p_adst, *p_e, *p_logits;
    __nv_bfloat16 *p_Ahi, *p_Alo, *p_Bhi, *p_Blo;
    cudaGetSymbolAddress((void**)&p_xp, g_xp);
    cudaGetSymbolAddress((void**)&p_h, g_h);
    cudaGetSymbolAddress((void**)&p_asrc, g_asrc);
    cudaGetSymbolAddress((void**)&p_adst, g_adst);
    cudaGetSymbolAddress((void**)&p_e, g_e);
    cudaGetSymbolAddress((void**)&p_logits, g_logits);
    cudaGetSymbolAddress((void**)&p_Ahi, g_Ahi);
    cudaGetSymbolAddress((void**)&p_Alo, g_Alo);
    cudaGetSymbolAddress((void**)&p_Bhi, g_Bhi);
    cudaGetSymbolAddress((void**)&p_Blo, g_Blo);

    cudaFuncSetAttribute(gemm_mma_kernel,
                         cudaFuncAttributeMaxDynamicSharedMemorySize, GEMM_SMEM);

    int has_loss = (out_size == N * C2v + 1) ? 1 : 0;
    int out_count = out_size - has_loss;
    if (out_count > N * C2v) out_count = N * C2v;

    // --- CSR build (shared by both layers) ---
    init_kernel<<<(N + 255) / 256, 256>>>(N);
    detect_mask_kernel<<<(N / 4 + 255) / 256, 256>>>((const unsigned int*)mask, N / 4);
    hist_kernel<<<(EP + 255) / 256, 256>>>(ei, E, N);
    offsets_kernel<<<(N + 255) / 256, 256>>>(N);
    scatter_kernel<<<(EP + 255) / 256, 256>>>(ei, E, N);

    dim3 ggrid(D / 128, (N + 127) / 128);

    // --- layer 1 ---
    split_kernel<<<592, 256>>>(x, p_Ahi, p_Alo, N * D);
    split_kernel<<<256, 256>>>(W1, p_Bhi, p_Blo, D * D);
    gemm_mma_kernel<<<ggrid, 256, GEMM_SMEM>>>(p_Ahi, p_Alo, p_Bhi, p_Blo, p_xp, N);
    att_kernel<<<(N + 7) / 8, 256>>>(p_xp, att_s1, att_d1, p_asrc, p_adst, N, H1v, C1v);
    score_kernel<<<(EP + 255) / 256, 256>>>(p_asrc, p_adst, ei, E, N, H1v);
    agg_kernel<<<N, 256>>>(p_xp, p_e, b1, p_h, ei, E, H1v, C1v, 0);

    // --- layer 2 ---
    split_kernel<<<592, 256>>>(p_h, p_Ahi, p_Alo, N * D);
    split_kernel<<<256, 256>>>(W2, p_Bhi, p_Blo, D * D);
    gemm_mma_kernel<<<ggrid, 256, GEMM_SMEM>>>(p_Ahi, p_Alo, p_Bhi, p_Blo, p_xp, N);
    att_kernel<<<(N + 7) / 8, 256>>>(p_xp, att_s2, att_d2, p_asrc, p_adst, N, H2v, C2v);
    score_kernel<<<(EP + 255) / 256, 256>>>(p_asrc, p_adst, ei, E, N, H2v);
    agg_kernel<<<N, 256>>>(p_xp, p_e, b2, p_logits, ei, E, H2v, C2v, 1);

    // --- output + loss ---
    copy_out_kernel<<<(out_count + 255) / 256, 256>>>(out_f + has_loss, out_count);
    loss_kernel<<<1024, 128>>>(y, mask, N);
    finalize_kernel<<<1, 1>>>(out_f, has_loss);
}

// round 4
// speedup vs baseline: 1.4723x; 1.0104x over previous
#include <cuda_runtime.h>
#include <cuda_bf16.h>
#include <math.h>
#include <stdint.h>

// Problem constants
#define D      512
#define NNODES 20000
#define NEDGES 100000
#define EPRIME (NEDGES + NNODES)
#define H1v    8
#define C1v    64
#define H2v    4
#define C2v    128
#define CHUNK  256

// ---------------- scratch (device globals; no allocation allowed) -------------
__device__ float g_xp[(size_t)NNODES * D];      // xp1, then reused as xp2
__device__ float g_h[(size_t)NNODES * D];       // hidden after layer 1
__device__ float g_asrc[(size_t)NNODES * H1v];
__device__ float g_adst[(size_t)NNODES * H1v];
__device__ float g_e[(size_t)EPRIME * H1v];     // edge scores (reused layer 2)
__device__ float g_logits[(size_t)NNODES * C2v];
__device__ int   g_deg[NNODES];
__device__ int   g_rowstart[NNODES];
__device__ int   g_cursor[NNODES];
__device__ int   g_csr[EPRIME];
__device__ float g_accum[2];
__device__ int   g_mask_byte;
__device__ int   g_total;
// bf16 hi/lo split buffers for tensor-core GEMM
__device__ __nv_bfloat16 g_Ahi[(size_t)NNODES * D];
__device__ __nv_bfloat16 g_Alo[(size_t)NNODES * D];
__device__ __nv_bfloat16 g_Bhi[(size_t)D * D];
__device__ __nv_bfloat16 g_Blo[(size_t)D * D];

// ---------------- helpers ----------------------------------------------------
__device__ __forceinline__ float warp_max(float v) {
    #pragma unroll
    for (int o = 16; o; o >>= 1) v = fmaxf(v, __shfl_xor_sync(0xffffffffu, v, o));
    return v;
}
__device__ __forceinline__ float warp_sum(float v) {
    #pragma unroll
    for (int o = 16; o; o >>= 1) v += __shfl_xor_sync(0xffffffffu, v, o);
    return v;
}

__device__ __forceinline__ void mma16816(float* c, const uint32_t* a, const uint32_t* b) {
    asm volatile(
        "mma.sync.aligned.m16n8k16.row.col.f32.bf16.bf16.f32 "
        "{%0,%1,%2,%3}, {%4,%5,%6,%7}, {%8,%9}, {%0,%1,%2,%3};\n"
        : "+f"(c[0]), "+f"(c[1]), "+f"(c[2]), "+f"(c[3])
        : "r"(a[0]), "r"(a[1]), "r"(a[2]), "r"(a[3]), "r"(b[0]), "r"(b[1]));
}
__device__ __forceinline__ void ldsm4(uint32_t* r, uint32_t addr) {
    asm volatile("ldmatrix.sync.aligned.m8n8.x4.shared.b16 {%0,%1,%2,%3}, [%4];\n"
        : "=r"(r[0]), "=r"(r[1]), "=r"(r[2]), "=r"(r[3]) : "r"(addr));
}
__device__ __forceinline__ void ldsm4t(uint32_t* r, uint32_t addr) {
    asm volatile("ldmatrix.sync.aligned.m8n8.x4.trans.shared.b16 {%0,%1,%2,%3}, [%4];\n"
        : "=r"(r[0]), "=r"(r[1]), "=r"(r[2]), "=r"(r[3]) : "r"(addr));
}
__device__ __forceinline__ void cpasync16(uint32_t dst, const void* src, int srcsize) {
    asm volatile("cp.async.cg.shared.global [%0], [%1], 16, %2;\n"
        :: "r"(dst), "l"(src), "r"(srcsize));
}
__device__ __forceinline__ void cp_commit() {
    asm volatile("cp.async.commit_group;\n");
}
template<int NW> __device__ __forceinline__ void cp_wait() {
    asm volatile("cp.async.wait_group %0;\n" :: "n"(NW));
}

// ---------------- init / CSR build -------------------------------------------
__global__ void init_kernel(int N) {
    int i = blockIdx.x * blockDim.x + threadIdx.x;
    if (i < N) g_deg[i] = 0;
    if (i == 0) { g_accum[0] = 0.f; g_accum[1] = 0.f; g_mask_byte = 0; g_total = 0; }
}

__global__ void detect_mask_kernel(const unsigned int* __restrict__ m, int nwords) {
    int i = blockIdx.x * blockDim.x + threadIdx.x;
    if (i < nwords) {
        unsigned v = m[i];
        if (v != 0u && v != 1u && v != 0x3F800000u) atomicOr(&g_mask_byte, 1);
    }
}

__global__ void hist_kernel(const int* __restrict__ ei, int E, int N) {
    int i = blockIdx.x * blockDim.x + threadIdx.x;
    if (i >= E + N) return;
    int d = (i < E) ? ei[E + i] : (i - E);
    atomicAdd(&g_deg[d], 1);
}

// Assign each node a contiguous segment (placement order is immaterial)
__global__ void offsets_kernel(int N) {
    int i = blockIdx.x * blockDim.x + threadIdx.x;
    if (i < N) {
        int base = atomicAdd(&g_total, g_deg[i]);
        g_rowstart[i] = base;
        g_cursor[i] = base;
    }
}

__global__ void scatter_kernel(const int* __restrict__ ei, int E, int N) {
    int i = blockIdx.x * blockDim.x + threadIdx.x;
    if (i >= E + N) return;
    int d = (i < E) ? ei[E + i] : (i - E);
    int pos = atomicAdd(&g_cursor[d], 1);
    g_csr[pos] = i;
}

// ---------------- bf16 hi/lo split --------------------------------------------
__global__ void split_kernel(const float* __restrict__ x,
                             __nv_bfloat16* __restrict__ hi,
                             __nv_bfloat16* __restrict__ lo, int n) {
    for (int i = blockIdx.x * blockDim.x + threadIdx.x; i < n; i += gridDim.x * blockDim.x) {
        float v = x[i];
        __nv_bfloat16 h = __float2bfloat16(v);
        hi[i] = h;
        lo[i] = __float2bfloat16(v - __bfloat162float(h));
    }
}

// ---------------- tensor-core GEMM: C[M,512] = A[M,512] @ B[512,512] -----------
// bf16 hi/lo split, 3 products into fp32 accumulators via mma.m16n8k16
#define LDA_S 40     // 32 + 8 pad (elems)
#define LDB_S 136    // 128 + 8 pad (elems)
#define A_HI_OFF 0
#define A_LO_OFF (128 * LDA_S * 2)                    // 10240
#define B_HI_OFF (A_LO_OFF * 2)                       // 20480
#define B_LO_OFF (B_HI_OFF + 32 * LDB_S * 2)          // 29184
#define STAGE_BYTES (B_LO_OFF + 32 * LDB_S * 2)       // 37888
#define GEMM_SMEM (2 * STAGE_BYTES)                   // 75776

extern __shared__ char smem_raw[];

__global__ __launch_bounds__(256, 1)
void gemm_mma_kernel(const __nv_bfloat16* __restrict__ Ahi,
                     const __nv_bfloat16* __restrict__ Alo,
                     const __nv_bfloat16* __restrict__ Bhi,
                     const __nv_bfloat16* __restrict__ Blo,
                     float* __restrict__ C, int M) {
    const int tid = threadIdx.x;
    const int lane = tid & 31;
    const int wid = tid >> 5;
    const int m0 = blockIdx.y * 128;
    const int n0 = blockIdx.x * 128;
    const int warp_m = wid >> 2;          // 0..1 -> 64 rows
    const int warp_n = wid & 3;           // 0..3 -> 32 cols
    const int m_base = warp_m * 64;
    const int n_base = warp_n * 32;

    uint32_t smem_u32 = (uint32_t)__cvta_generic_to_shared(smem_raw);

    // per-thread load slots
    const int arow0 = tid >> 2, acol0 = (tid & 3) * 8;         // + row 64 for second chunk
    const int brow0 = tid >> 4, bcol0 = (tid & 15) * 8;        // + row 16 for second chunk

    float acc[4][4][4];
    #pragma unroll
    for (int i = 0; i < 4; i++)
        #pragma unroll
        for (int j = 0; j < 4; j++)
            #pragma unroll
            for (int k = 0; k < 4; k++) acc[i][j][k] = 0.f;

    const int NIT = D / 32;   // 16

    auto load_stage = [&](int it, int s) {
        int k0 = it * 32;
        uint32_t base = smem_u32 + s * STAGE_BYTES;
        #pragma unroll
        for (int c = 0; c < 2; c++) {
            int row = arow0 + c * 64;
            int gr = m0 + row;
            int ok = (gr < M) ? 16 : 0;
            size_t goff = (size_t)gr * D + k0 + acol0;
            uint32_t soff = (uint32_t)(row * LDA_S + acol0) * 2;
            cpasync16(base + A_HI_OFF + soff, Ahi + goff, ok);
            cpasync16(base + A_LO_OFF + soff, Alo + goff, ok);
        }
        #pragma unroll
        for (int c = 0; c < 2; c++) {
            int row = brow0 + c * 16;
            size_t goff = (size_t)(k0 + row) * D + n0 + bcol0;
            uint32_t soff = (uint32_t)(row * LDB_S + bcol0) * 2;
            cpasync16(base + B_HI_OFF + soff, Bhi + goff, 16);
            cpasync16(base + B_LO_OFF + soff, Blo + goff, 16);
        }
    };

    load_stage(0, 0);
    cp_commit();

    for (int it = 0; it < NIT; it++) {
        if (it + 1 < NIT) {
            load_stage(it + 1, (it + 1) & 1);
            cp_commit();
            cp_wait<1>();
        } else {
            cp_wait<0>();
        }
        __syncthreads();

        uint32_t stg = smem_u32 + (it & 1) * STAGE_BYTES;
        #pragma unroll
        for (int kk = 0; kk < 2; kk++) {
            int kof = kk * 16;
            uint32_t ahi[4][4], alo[4][4];
            #pragma unroll
            for (int mt = 0; mt < 4; mt++) {
                uint32_t off = (uint32_t)((m_base + mt * 16 + (lane & 15)) * LDA_S
                                          + kof + 8 * (lane >> 4)) * 2;
                ldsm4(ahi[mt], stg + A_HI_OFF + off);
                ldsm4(alo[mt], stg + A_LO_OFF + off);
            }
            uint32_t bhi[4][2], blo[4][2];
            #pragma unroll
            for (int p = 0; p < 2; p++) {
                uint32_t off = (uint32_t)((kof + (lane & 7) + 8 * ((lane >> 3) & 1)) * LDB_S
                                          + n_base + p * 16 + 8 * (lane >> 4)) * 2;
                uint32_t r[4];
                ldsm4t(r, stg + B_HI_OFF + off);
                bhi[p * 2][0] = r[0]; bhi[p * 2][1] = r[1];
                bhi[p * 2 + 1][0] = r[2]; bhi[p * 2 + 1][1] = r[3];
                ldsm4t(r, stg + B_LO_OFF + off);
                blo[p * 2][0] = r[0]; blo[p * 2][1] = r[1];
                blo[p * 2 + 1][0] = r[2]; blo[p * 2 + 1][1] = r[3];
            }
            #pragma unroll
            for (int mt = 0; mt < 4; mt++)
                #pragma unroll
                for (int nt = 0; nt < 4; nt++) {
                    mma16816(acc[mt][nt], ahi[mt], bhi[nt]);
                    mma16816(acc[mt][nt], ahi[mt], blo[nt]);
                    mma16816(acc[mt][nt], alo[mt], bhi[nt]);
                }
        }
        __syncthreads();
    }

    // epilogue
    const int gid = lane >> 2, t4 = lane & 3;
    #pragma unroll
    for (int mt = 0; mt < 4; mt++) {
        int r0 = m0 + m_base + mt * 16 + gid;
        int r1 = r0 + 8;
        #pragma unroll
        for (int nt = 0; nt < 4; nt++) {
            int col = n0 + n_base + nt * 8 + t4 * 2;
            if (r0 < M) *(float2*)&C[(size_t)r0 * D + col] = make_float2(acc[mt][nt][0], acc[mt][nt][1]);
            if (r1 < M) *(float2*)&C[(size_t)r1 * D + col] = make_float2(acc[mt][nt][2], acc[mt][nt][3]);
        }
    }
}

// ---------------- per-node attention dot products ----------------------------
__global__ void att_kernel(const float* __restrict__ xp,
                           const float* __restrict__ a_src, const float* __restrict__ a_dst,
                           float* __restrict__ asrc, float* __restrict__ adst,
                           int N, int H, int C) {
    int warp = (blockIdx.x * blockDim.x + threadIdx.x) >> 5;
    int lane = threadIdx.x & 31;
    if (warp >= N) return;
    const float* row = xp + (size_t)warp * D;
    for (int h = 0; h < H; h++) {
        float ss = 0.f, sd = 0.f;
        for (int j = lane; j < C; j += 32) {
            float xv = row[h * C + j];
            ss += xv * a_src[h * C + j];
            sd += xv * a_dst[h * C + j];
        }
        ss = warp_sum(ss);
        sd = warp_sum(sd);
        if (lane == 0) { asrc[warp * H + h] = ss; adst[warp * H + h] = sd; }
    }
}

// ---------------- per-edge leaky-relu scores ---------------------------------
__global__ void score_kernel(const float* __restrict__ asrc, const float* __restrict__ adst,
                             const int* __restrict__ ei, int E, int N, int H) {
    int i = blockIdx.x * blockDim.x + threadIdx.x;
    if (i >= E + N) return;
    int s, d;
    if (i < E) { s = ei[i]; d = ei[E + i]; } else { s = d = i - E; }
    for (int h = 0; h < H; h++) {
        float v = asrc[s * H + h] + adst[d * H + h];
        g_e[(size_t)i * H + h] = v > 0.f ? v : 0.2f * v;
    }
}

// ---------------- per-dst softmax + aggregate (block per node) ---------------
__global__ __launch_bounds__(256)
void agg_kernel(const float* __restrict__ xp, const float* __restrict__ e,
                const float* __restrict__ bias, float* __restrict__ out,
                const int* __restrict__ ei, int E, int H, int C, int mode) {
    __shared__ float sh_alpha[CHUNK * H1v];
    __shared__ int   sh_src[CHUNK];
    __shared__ float sh_m[H1v], sh_s[H1v];
    __shared__ float sh_red[512];
    int n = blockIdx.x;
    int tid = threadIdx.x;
    int w = tid >> 5, lane = tid & 31;
    int beg = g_rowstart[n], end = beg + g_deg[n];

    if (w < H) {
        float m = -1e30f;
        for (int i = beg + lane; i < end; i += 32)
            m = fmaxf(m, e[(size_t)g_csr[i] * H + w]);
        m = warp_max(m);
        float s = 0.f;
        for (int i = beg + lane; i < end; i += 32)
            s += expf(e[(size_t)g_csr[i] * H + w] - m);
        s = warp_sum(s);
        if (lane == 0) { sh_m[w] = m; sh_s[w] = s + 1e-16f; }
    }
    __syncthreads();

    int h0 = tid / C, h1 = (tid + 256) / C;
    float acc0 = 0.f, acc1 = 0.f;
    for (int cs = beg; cs < end; cs += CHUNK) {
        int cn = min(CHUNK, end - cs);
        for (int idx = tid; idx < cn; idx += 256) {
            int eid = g_csr[cs + idx];
            sh_src[idx] = (eid < E) ? ei[eid] : (eid - E);
        }
        for (int idx = tid; idx < cn * H; idx += 256) {
            int i = idx / H, h = idx - i * H;
            int eid = g_csr[cs + i];
            sh_alpha[i * H + h] = expf(e[(size_t)eid * H + h] - sh_m[h]) / sh_s[h];
        }
        __syncthreads();
        for (int i = 0; i < cn; i++) {
            const float* row = xp + (size_t)sh_src[i] * D;
            acc0 += sh_alpha[i * H + h0] * row[tid];
            acc1 += sh_alpha[i * H + h1] * row[tid + 256];
        }
        __syncthreads();
    }

    if (mode == 0) {
        float v0 = acc0 + bias[tid];
        float v1 = acc1 + bias[tid + 256];
        out[(size_t)n * D + tid]       = v0 > 0.f ? v0 : expm1f(v0);
        out[(size_t)n * D + tid + 256] = v1 > 0.f ? v1 : expm1f(v1);
    } else {
        sh_red[tid] = acc0;
        sh_red[tid + 256] = acc1;
        __syncthreads();
        if (tid < C) {
            float s = 0.f;
            for (int h = 0; h < H; h++) s += sh_red[h * C + tid];
            out[(size_t)n * C + tid] = s / (float)H + bias[tid];
        }
    }
}

// ---------------- loss --------------------------------------------------------
__global__ void copy_out_kernel(float* __restrict__ dst, int count) {
    int i = blockIdx.x * blockDim.x + threadIdx.x;
    if (i < count) dst[i] = g_logits[i];
}

__global__ __launch_bounds__(128)
void loss_kernel(const int* __restrict__ y, const int* __restrict__ mask, int N) {
    __shared__ float red[128];
    int tid = threadIdx.x;
    float lce = 0.f, lw = 0.f;
    int byte_mode = g_mask_byte;
    for (int n = blockIdx.x; n < N; n += gridDim.x) {
        float v = g_logits[(size_t)n * C2v + tid];
        red[tid] = v;
        __syncthreads();
        #pragma unroll
        for (int o = 64; o; o >>= 1) {
            if (tid < o) red[tid] = fmaxf(red[tid], red[tid + o]);
            __syncthreads();
        }
        float m = red[0];
        __syncthreads();
        red[tid] = expf(v - m);
        __syncthreads();
        #pragma unroll
        for (int o = 64; o; o >>= 1) {
            if (tid < o) red[tid] += red[tid + o];
            __syncthreads();
        }
        if (tid == 0) {
            bool mv = byte_mode ? (((const unsigned char*)mask)[n] != 0) : (mask[n] != 0);
            if (mv) {
                float lse = m + logf(red[0]);
                lce += lse - g_logits[(size_t)n * C2v + y[n]];
                lw += 1.f;
            }
        }
        __syncthreads();
    }
    if (tid == 0) {
        atomicAdd(&g_accum[0], lce);
        atomicAdd(&g_accum[1], lw);
    }
}

__global__ void finalize_kernel(float* d_out, int write_loss) {
    if (write_loss) d_out[0] = g_accum[0] / g_accum[1];
}

// ---------------- launch ------------------------------------------------------
extern "C" void kernel_launch(void* const* d_in, const int* in_sizes, int n_in,
                              void* d_out, int out_size) {
    const float* x       = (const float*)d_in[0];
    const int*   ei      = (const int*)d_in[1];
    const int*   y       = (const int*)d_in[2];
    const int*   mask    = (const int*)d_in[3];
    const float* W1      = (const float*)d_in[4];
    const float* att_s1  = (const float*)d_in[5];
    const float* att_d1  = (const float*)d_in[6];
    const float* b1      = (const float*)d_in[7];
    const float* W2      = (const float*)d_in[8];
    const float* att_s2  = (const float*)d_in[9];
    const float* att_d2  = (const float*)d_in[10];
    const float* b2      = (const float*)d_in[11];
    float* out_f = (float*)d_out;

    int N = in_sizes[0] / D;        // 20000
    int E = in_sizes[1] / 2;        // 100000
    int EP = E + N;

    float *p_xp, *p_h, *p_asrc, *p_adst, *p_e, *p_logits;
    __nv_bfloat16 *p_Ahi, *p_Alo, *p_Bhi, *p_Blo;
    cudaGetSymbolAddress((void**)&p_xp, g_xp);
    cudaGetSymbolAddress((void**)&p_h, g_h);
    cudaGetSymbolAddress((void**)&p_asrc, g_asrc);
    cudaGetSymbolAddress((void**)&p_adst, g_adst);
    cudaGetSymbolAddress((void**)&p_e, g_e);
    cudaGetSymbolAddress((void**)&p_logits, g_logits);
    cudaGetSymbolAddress((void**)&p_Ahi, g_Ahi);
    cudaGetSymbolAddress((void**)&p_Alo, g_Alo);
    cudaGetSymbolAddress((void**)&p_Bhi, g_Bhi);
    cudaGetSymbolAddress((void**)&p_Blo, g_Blo);

    cudaFuncSetAttribute(gemm_mma_kernel,
                         cudaFuncAttributeMaxDynamicSharedMemorySize, GEMM_SMEM);

    int has_loss = (out_size == N * C2v + 1) ? 1 : 0;
    int out_count = out_size - has_loss;
    if (out_count > N * C2v) out_count = N * C2v;

    // --- CSR build (shared by both layers) ---
    init_kernel<<<(N + 255) / 256, 256>>>(N);
    detect_mask_kernel<<<(N / 4 + 255) / 256, 256>>>((const unsigned int*)mask, N / 4);
    hist_kernel<<<(EP + 255) / 256, 256>>>(ei, E, N);
    offsets_kernel<<<(N + 255) / 256, 256>>>(N);
    scatter_kernel<<<(EP + 255) / 256, 256>>>(ei, E, N);

    dim3 ggrid(D / 128, (N + 127) / 128);

    // --- layer 1 ---
    split_kernel<<<592, 256>>>(x, p_Ahi, p_Alo, N * D);
    split_kernel<<<256, 256>>>(W1, p_Bhi, p_Blo, D * D);
    gemm_mma_kernel<<<ggrid, 256, GEMM_SMEM>>>(p_Ahi, p_Alo, p_Bhi, p_Blo, p_xp, N);
    att_kernel<<<(N + 7) / 8, 256>>>(p_xp, att_s1, att_d1, p_asrc, p_adst, N, H1v, C1v);
    score_kernel<<<(EP + 255) / 256, 256>>>(p_asrc, p_adst, ei, E, N, H1v);
    agg_kernel<<<N, 256>>>(p_xp, p_e, b1, p_h, ei, E, H1v, C1v, 0);

    // --- layer 2 ---
    split_kernel<<<592, 256>>>(p_h, p_Ahi, p_Alo, N * D);
    split_kernel<<<256, 256>>>(W2, p_Bhi, p_Blo, D * D);
    gemm_mma_kernel<<<ggrid, 256, GEMM_SMEM>>>(p_Ahi, p_Alo, p_Bhi, p_Blo, p_xp, N);
    att_kernel<<<(N + 7) / 8, 256>>>(p_xp, att_s2, att_d2, p_asrc, p_adst, N, H2v, C2v);
    score_kernel<<<(EP + 255) / 256, 256>>>(p_asrc, p_adst, ei, E, N, H2v);
    agg_kernel<<<N, 256>>>(p_xp, p_e, b2, p_logits, ei, E, H2v, C2v, 1);

    // --- output + loss ---
    copy_out_kernel<<<(out_count + 255) / 256, 256>>>(out_f + has_loss, out_count);
    loss_kernel<<<1024, 128>>>(y, mask, N);
    finalize_kernel<<<1, 1>>>(out_f, has_loss);
}